// round 4
// baseline (speedup 1.0000x reference)
#include <cuda_runtime.h>
#include <math.h>

#define DD 64
#define NN 100000
#define EE 1600000

// ---------------- scratch (device globals; no runtime allocation) ----------------
__device__ float g_x1[(size_t)NN * DD];
__device__ float g_x2[(size_t)NN * DD];
__device__ float g_x3[(size_t)NN * DD];
__device__ float g_x4[(size_t)NN * DD];
__device__ float g_sums[(size_t)NN * DD];
__device__ float g_cnt[NN];
__device__ double g_est[2 * DD];   // edge BN: [0:64) sum, [64:128) sumsq
__device__ double g_vst[2 * DD];   // node BN: [0:64) sum, [64:128) sumsq
__device__ float g_aff[4 * DD];    // vscale, vshift, escale, eshift

__device__ __forceinline__ float siluf(float z) {
    return z * __fdividef(1.0f, 1.0f + __expf(-z));
}
__device__ __forceinline__ float sigf(float z) {
    return __fdividef(1.0f, 1.0f + __expf(-z));
}
__device__ __forceinline__ void red_add_v4(float* p, float4 v) {
    asm volatile("red.global.add.v4.f32 [%0], {%1, %2, %3, %4};"
                 :: "l"(p), "f"(v.x), "f"(v.y), "f"(v.z), "f"(v.w) : "memory");
}
__device__ __forceinline__ void red_add_f32(float* p, float v) {
    asm volatile("red.global.add.f32 [%0], %1;" :: "l"(p), "f"(v) : "memory");
}

// ---------------- zero scratch accumulators ----------------
__global__ void k_zero() {
    int i = blockIdx.x * blockDim.x + threadIdx.x;
    int stride = gridDim.x * blockDim.x;
    for (int t = i; t < NN * DD; t += stride) g_sums[t] = 0.0f;
    for (int t = i; t < NN; t += stride) g_cnt[t] = 0.0f;
    if (i < 2 * DD) { g_est[i] = 0.0; g_vst[i] = 0.0; }
}

// ---------------- node GEMMs: x1..x4 = x @ Wm^T + bm ----------------
// block: 256 threads, 128 nodes/tile; dyn smem: xT[64][128] + Ws[64][64] + bs[64]
__global__ void __launch_bounds__(256) k_node_gemm(
    const float* __restrict__ x,
    const float* __restrict__ W1, const float* __restrict__ b1,
    const float* __restrict__ W2, const float* __restrict__ b2,
    const float* __restrict__ W3, const float* __restrict__ b3,
    const float* __restrict__ W4, const float* __restrict__ b4,
    int N)
{
    extern __shared__ float sm[];
    float* xT = sm;                 // [k][node] 64*128
    float* Ws = sm + 64 * 128;      // [k][j]    64*64
    float* bs = Ws + 64 * 64;       // [64]
    int tid = threadIdx.x;
    int nb = blockIdx.x * 128;

    // fill xT (transposed): thread -> (node = tid/2, half of k)
    {
        int nl = tid >> 1, h = tid & 1;
        int node = nb + nl;
        const float4* xr = (const float4*)(x + (size_t)node * DD + h * 32);
        #pragma unroll
        for (int q = 0; q < 8; q++) {
            float4 v = (node < N) ? __ldg(&xr[q]) : make_float4(0.f, 0.f, 0.f, 0.f);
            int kb = h * 32 + q * 4;
            xT[(kb + 0) * 128 + nl] = v.x;
            xT[(kb + 1) * 128 + nl] = v.y;
            xT[(kb + 2) * 128 + nl] = v.z;
            xT[(kb + 3) * 128 + nl] = v.w;
        }
    }

    const float* Wm[4] = {W1, W2, W3, W4};
    const float* bm[4] = {b1, b2, b3, b4};
    float* om[4] = {g_x1, g_x2, g_x3, g_x4};

    int tr = tid >> 3;       // 0..31 -> nodes tr*4..+4
    int tc = tid & 7;        // 0..7  -> feats tc*8..+8
    int fb = tc * 8;

    #pragma unroll 1
    for (int m = 0; m < 4; m++) {
        __syncthreads();
        const float* W = Wm[m];
        #pragma unroll
        for (int p = 0; p < 16; p++) {
            int idx = p * 256 + tid;            // idx = j*64 + k
            Ws[(idx & 63) * 64 + (idx >> 6)] = __ldg(&W[idx]);
        }
        if (tid < 64) bs[tid] = __ldg(&bm[m][tid]);
        __syncthreads();

        float acc[4][8];
        #pragma unroll
        for (int i = 0; i < 4; i++)
            #pragma unroll
            for (int j = 0; j < 8; j++) acc[i][j] = 0.0f;

        #pragma unroll 4
        for (int k = 0; k < 64; k++) {
            float4 a  = *(const float4*)&xT[k * 128 + tr * 4];
            float4 c0 = *(const float4*)&Ws[k * 64 + fb];
            float4 c1 = *(const float4*)&Ws[k * 64 + fb + 4];
            float av[4] = {a.x, a.y, a.z, a.w};
            float bv[8] = {c0.x, c0.y, c0.z, c0.w, c1.x, c1.y, c1.z, c1.w};
            #pragma unroll
            for (int i = 0; i < 4; i++)
                #pragma unroll
                for (int j = 0; j < 8; j++)
                    acc[i][j] = fmaf(av[i], bv[j], acc[i][j]);
        }

        float* out = om[m];
        #pragma unroll
        for (int i = 0; i < 4; i++) {
            int node = nb + tr * 4 + i;
            if (node < N) {
                float4 o0 = make_float4(acc[i][0] + bs[fb + 0], acc[i][1] + bs[fb + 1],
                                        acc[i][2] + bs[fb + 2], acc[i][3] + bs[fb + 3]);
                float4 o1 = make_float4(acc[i][4] + bs[fb + 4], acc[i][5] + bs[fb + 5],
                                        acc[i][6] + bs[fb + 6], acc[i][7] + bs[fb + 7]);
                *(float4*)&out[(size_t)node * DD + fb]     = o0;
                *(float4*)&out[(size_t)node * DD + fb + 4] = o1;
            }
        }
    }
}

// ---------------- edge main pass ----------------
// Per 256-edge tile: y = w0@We^T + be + x3[src] + x4[dst] -> ybuf, edge-BN stats,
// and sigmoid(w0)*x2[dst] scatter-add into g_sums[src] (+ counts).
// dyn smem: w0T[64][256] (64KB) + WeT[64][64] (16KB)
__global__ void __launch_bounds__(256) k_edge_main(
    const float* __restrict__ ea, const float* __restrict__ We, const float* __restrict__ be,
    const int* __restrict__ esrc, const int* __restrict__ edst,
    float* __restrict__ ybuf, int E)
{
    extern __shared__ float sm[];
    float* w0T = sm;                  // [k][edge] 64*256
    float* WeT = sm + 64 * 256;       // [k][j]    64*64
    __shared__ int srcs[256], dsts[256];
    __shared__ float ssum[64], ssq[64], bes[64];

    int tid = threadIdx.x;
    int e0 = blockIdx.x * 256;
    int e = e0 + tid;
    bool valid = (e < E);

    srcs[tid] = valid ? __ldg(&esrc[e]) : 0;
    dsts[tid] = valid ? __ldg(&edst[e]) : 0;
    if (tid < 64) { ssum[tid] = 0.0f; ssq[tid] = 0.0f; bes[tid] = __ldg(&be[tid]); }

    #pragma unroll
    for (int p = 0; p < 16; p++) {
        int idx = p * 256 + tid;            // idx = j*64 + k
        WeT[(idx & 63) * 64 + (idx >> 6)] = __ldg(&We[idx]);
    }
    {
        const float4* er = (const float4*)(ea + (size_t)e * DD);
        #pragma unroll
        for (int q = 0; q < 16; q++) {
            float4 v = valid ? __ldg(&er[q]) : make_float4(0.f, 0.f, 0.f, 0.f);
            w0T[(q * 4 + 0) * 256 + tid] = v.x;
            w0T[(q * 4 + 1) * 256 + tid] = v.y;
            w0T[(q * 4 + 2) * 256 + tid] = v.z;
            w0T[(q * 4 + 3) * 256 + tid] = v.w;
        }
    }
    __syncthreads();

    int tr = tid >> 3;          // 0..31 -> edges tr*8..+8
    int tc = tid & 7;           // 0..7  -> feats tc*8..+8
    int eb = tr * 8, fb = tc * 8;

    float acc[8][8];
    #pragma unroll
    for (int i = 0; i < 8; i++)
        #pragma unroll
        for (int j = 0; j < 8; j++) acc[i][j] = 0.0f;

    #pragma unroll 4
    for (int k = 0; k < 64; k++) {
        float4 a0 = *(const float4*)&w0T[k * 256 + eb];
        float4 a1 = *(const float4*)&w0T[k * 256 + eb + 4];
        float4 c0 = *(const float4*)&WeT[k * 64 + fb];
        float4 c1 = *(const float4*)&WeT[k * 64 + fb + 4];
        float av[8] = {a0.x, a0.y, a0.z, a0.w, a1.x, a1.y, a1.z, a1.w};
        float bv[8] = {c0.x, c0.y, c0.z, c0.w, c1.x, c1.y, c1.z, c1.w};
        #pragma unroll
        for (int i = 0; i < 8; i++)
            #pragma unroll
            for (int j = 0; j < 8; j++)
                acc[i][j] = fmaf(av[i], bv[j], acc[i][j]);
    }

    // epilogue: bias + x3[src] + x4[dst], stats, store y
    float bb[8];
    #pragma unroll
    for (int j = 0; j < 8; j++) bb[j] = bes[fb + j];

    float ps[8], pq[8];
    #pragma unroll
    for (int j = 0; j < 8; j++) { ps[j] = 0.0f; pq[j] = 0.0f; }

    #pragma unroll
    for (int i = 0; i < 8; i++) {
        int el = eb + i;
        int eg = e0 + el;
        if (eg < E) {
            int s = srcs[el], d = dsts[el];
            const float* x3r = g_x3 + (size_t)s * DD + fb;
            const float* x4r = g_x4 + (size_t)d * DD + fb;
            float4 c0 = __ldg((const float4*)x3r);
            float4 c1 = __ldg((const float4*)(x3r + 4));
            float4 d0 = __ldg((const float4*)x4r);
            float4 d1 = __ldg((const float4*)(x4r + 4));
            float g34[8] = {c0.x + d0.x, c0.y + d0.y, c0.z + d0.z, c0.w + d0.w,
                            c1.x + d1.x, c1.y + d1.y, c1.z + d1.z, c1.w + d1.w};
            float y[8];
            #pragma unroll
            for (int j = 0; j < 8; j++) {
                y[j] = acc[i][j] + bb[j] + g34[j];
                ps[j] += y[j];
                pq[j] += y[j] * y[j];
            }
            float* yr = ybuf + (size_t)eg * DD + fb;
            *(float4*)yr       = make_float4(y[0], y[1], y[2], y[3]);
            *(float4*)(yr + 4) = make_float4(y[4], y[5], y[6], y[7]);
        }
    }
    #pragma unroll
    for (int j = 0; j < 8; j++) {
        atomicAdd(&ssum[fb + j], ps[j]);
        atomicAdd(&ssq[fb + j], pq[j]);
    }
    __syncthreads();
    if (tid < 64) {
        atomicAdd(&g_est[tid], (double)ssum[tid]);
        atomicAdd(&g_est[64 + tid], (double)ssq[tid]);
    }

    // scatter: sigmoid(w0)*x2[dst] -> g_sums[src], counts[src]++
    if (valid) {
        int s = srcs[tid], d = dsts[tid];
        const float4* x2r = (const float4*)(g_x2 + (size_t)d * DD);
        float* sp = g_sums + (size_t)s * DD;
        #pragma unroll
        for (int q = 0; q < 16; q++) {
            float4 xv = __ldg(&x2r[q]);
            float w0 = w0T[(q * 4 + 0) * 256 + tid];
            float w1 = w0T[(q * 4 + 1) * 256 + tid];
            float w2 = w0T[(q * 4 + 2) * 256 + tid];
            float w3 = w0T[(q * 4 + 3) * 256 + tid];
            float4 r;
            r.x = xv.x * sigf(w0);
            r.y = xv.y * sigf(w1);
            r.z = xv.z * sigf(w2);
            r.w = xv.w * sigf(w3);
            red_add_v4(sp + q * 4, r);
        }
        red_add_f32(&g_cnt[s], 1.0f);
    }
}

// ---------------- node stats: yv = x1 + sums/max(cnt,1) (in-place in g_x1) + BN stats ---------
__global__ void __launch_bounds__(256) k_node_stats(int N) {
    __shared__ float ssum[64], ssq[64];
    int tid = threadIdx.x;
    if (tid < 64) { ssum[tid] = 0.0f; ssq[tid] = 0.0f; }
    __syncthreads();
    int f = tid & 63;
    int g = tid >> 6;       // 0..3, 16 nodes each
    int nb = blockIdx.x * 64;
    float ls = 0.0f, lq = 0.0f;
    for (int i = 0; i < 16; i++) {
        int node = nb + g * 16 + i;
        if (node < N) {
            float c = g_cnt[node];
            float inv = __fdividef(1.0f, fmaxf(c, 1.0f));
            size_t idx = (size_t)node * DD + f;
            float yv = g_x1[idx] + g_sums[idx] * inv;
            g_x1[idx] = yv;
            ls += yv;
            lq += yv * yv;
        }
    }
    atomicAdd(&ssum[f], ls);
    atomicAdd(&ssq[f], lq);
    __syncthreads();
    if (tid < 64) {
        atomicAdd(&g_vst[tid], (double)ssum[tid]);
        atomicAdd(&g_vst[64 + tid], (double)ssq[tid]);
    }
}

// ---------------- fold BN stats into scale/shift ----------------
__global__ void k_finalize(const float* __restrict__ vg, const float* __restrict__ vb,
                           const float* __restrict__ eg2, const float* __restrict__ eb2,
                           int N, int E)
{
    int f = threadIdx.x;
    if (f < 64) {
        double mv = g_vst[f] / (double)N;
        double varv = g_vst[64 + f] / (double)N - mv * mv;
        float scv = __ldg(&vg[f]) * rsqrtf((float)varv + 1e-5f);
        g_aff[f] = scv;
        g_aff[64 + f] = __ldg(&vb[f]) - (float)mv * scv;

        double me = g_est[f] / (double)E;
        double vare = g_est[64 + f] / (double)E - me * me;
        float sce = __ldg(&eg2[f]) * rsqrtf((float)vare + 1e-5f);
        g_aff[128 + f] = sce;
        g_aff[192 + f] = __ldg(&eb2[f]) - (float)me * sce;
    }
}

// ---------------- x_out = x + silu(bn(yv)) ----------------
__global__ void __launch_bounds__(256) k_node_out(const float* __restrict__ x,
                                                  float* __restrict__ out, int N)
{
    int i = blockIdx.x * blockDim.x + threadIdx.x;   // float4 index
    if (i < N * 16) {
        int f0 = (i & 15) * 4;
        float4 yv = *(const float4*)&g_x1[(size_t)i * 4];
        float4 xv = __ldg(((const float4*)x) + i);
        float4 sc = *(const float4*)&g_aff[f0];
        float4 sh = *(const float4*)&g_aff[64 + f0];
        float4 o;
        float z;
        z = fmaf(yv.x, sc.x, sh.x); o.x = xv.x + siluf(z);
        z = fmaf(yv.y, sc.y, sh.y); o.y = xv.y + siluf(z);
        z = fmaf(yv.z, sc.z, sh.z); o.z = xv.z + siluf(z);
        z = fmaf(yv.w, sc.w, sh.w); o.w = xv.w + siluf(z);
        ((float4*)out)[i] = o;
    }
}

// ---------------- w_out = w0 + silu(bn(y)) (y in-place in output buffer) ----------------
__global__ void __launch_bounds__(256) k_edge_out(const float* __restrict__ ea,
                                                  float* __restrict__ wout, int E)
{
    int i = blockIdx.x * blockDim.x + threadIdx.x;   // float4 index
    if (i < E * 16) {
        int f0 = (i & 15) * 4;
        float4 yv = ((const float4*)wout)[i];
        float4 w0 = __ldg(((const float4*)ea) + i);
        float4 sc = *(const float4*)&g_aff[128 + f0];
        float4 sh = *(const float4*)&g_aff[192 + f0];
        float4 o;
        float z;
        z = fmaf(yv.x, sc.x, sh.x); o.x = w0.x + siluf(z);
        z = fmaf(yv.y, sc.y, sh.y); o.y = w0.y + siluf(z);
        z = fmaf(yv.z, sc.z, sh.z); o.z = w0.z + siluf(z);
        z = fmaf(yv.w, sc.w, sh.w); o.w = w0.w + siluf(z);
        ((float4*)wout)[i] = o;
    }
}

// ---------------- launch ----------------
extern "C" void kernel_launch(void* const* d_in, const int* in_sizes, int n_in,
                              void* d_out, int out_size)
{
    const float* x  = (const float*)d_in[0];
    const float* ea = (const float*)d_in[1];
    const float* W1 = (const float*)d_in[2];  const float* b1 = (const float*)d_in[3];
    const float* W2 = (const float*)d_in[4];  const float* b2 = (const float*)d_in[5];
    const float* W3 = (const float*)d_in[6];  const float* b3 = (const float*)d_in[7];
    const float* W4 = (const float*)d_in[8];  const float* b4 = (const float*)d_in[9];
    const float* We = (const float*)d_in[10]; const float* be = (const float*)d_in[11];
    const float* vg = (const float*)d_in[12]; const float* vb = (const float*)d_in[13];
    const float* eg = (const float*)d_in[14]; const float* eb = (const float*)d_in[15];
    const int*   ei = (const int*)d_in[16];

    int N = in_sizes[0] / DD;
    int E = in_sizes[16] / 2;

    float* out = (float*)d_out;
    float* ybuf = out + (size_t)N * DD;   // w_out region doubles as y scratch

    // dynamic smem opt-ins (idempotent; first call happens before graph capture)
    (void)cudaFuncSetAttribute(k_node_gemm, cudaFuncAttributeMaxDynamicSharedMemorySize,
                               (64 * 128 + 64 * 64 + 64) * (int)sizeof(float));
    (void)cudaFuncSetAttribute(k_edge_main, cudaFuncAttributeMaxDynamicSharedMemorySize,
                               (64 * 256 + 64 * 64) * (int)sizeof(float));

    k_zero<<<256, 256>>>();
    k_node_gemm<<<(N + 127) / 128, 256, (64 * 128 + 64 * 64 + 64) * sizeof(float)>>>(
        x, W1, b1, W2, b2, W3, b3, W4, b4, N);
    k_edge_main<<<(E + 255) / 256, 256, (64 * 256 + 64 * 64) * sizeof(float)>>>(
        ea, We, be, ei, ei + E, ybuf, E);
    k_node_stats<<<(N + 63) / 64, 256>>>(N);
    k_finalize<<<1, 64>>>(vg, vb, eg, eb, N, E);
    k_node_out<<<(N * 16 + 255) / 256, 256>>>(x, out, N);
    k_edge_out<<<(E * 16 + 255) / 256, 256>>>(ea, ybuf, E);
}

// round 5
// speedup vs baseline: 1.1084x; 1.1084x over previous
#include <cuda_runtime.h>
#include <math.h>

#define DD 64
#define NN 100000
#define EE 1600000

typedef unsigned long long u64;

// ---------------- scratch (device globals; no runtime allocation) ----------------
__device__ float g_x1[(size_t)NN * DD];
__device__ float g_x2[(size_t)NN * DD];
__device__ float g_x3[(size_t)NN * DD];
__device__ float g_x4[(size_t)NN * DD];
__device__ float g_sums[(size_t)NN * DD];
__device__ float g_cnt[NN];
__device__ double g_est[2 * DD];   // edge BN: [0:64) sum, [64:128) sumsq
__device__ double g_vst[2 * DD];   // node BN: [0:64) sum, [64:128) sumsq
__device__ float g_aff[4 * DD];    // vscale, vshift, escale, eshift

__device__ __forceinline__ float siluf(float z) {
    return z * __fdividef(1.0f, 1.0f + __expf(-z));
}
__device__ __forceinline__ float sigf(float z) {
    return __fdividef(1.0f, 1.0f + __expf(-z));
}
__device__ __forceinline__ void red_add_v4(float* p, float4 v) {
    asm volatile("red.global.add.v4.f32 [%0], {%1, %2, %3, %4};"
                 :: "l"(p), "f"(v.x), "f"(v.y), "f"(v.z), "f"(v.w) : "memory");
}
__device__ __forceinline__ void red_add_f32(float* p, float v) {
    asm volatile("red.global.add.f32 [%0], %1;" :: "l"(p), "f"(v) : "memory");
}

// ---- packed f32x2 FMA (FFMA2: 2x fp32 FMA throughput; PTX-only, ptxas won't auto-fuse) ----
__device__ __forceinline__ u64 pk2(float x, float y) {
    u64 d; asm("mov.b64 %0, {%1, %2};" : "=l"(d) : "f"(x), "f"(y)); return d;
}
__device__ __forceinline__ void upk2(u64 v, float& x, float& y) {
    asm("mov.b64 {%0, %1}, %2;" : "=f"(x), "=f"(y) : "l"(v));
}
__device__ __forceinline__ u64 ffma2(u64 a, u64 b, u64 c) {
    u64 d; asm("fma.rn.f32x2 %0, %1, %2, %3;" : "=l"(d) : "l"(a), "l"(b), "l"(c)); return d;
}

// ---------------- zero scratch accumulators ----------------
__global__ void k_zero() {
    int i = blockIdx.x * blockDim.x + threadIdx.x;
    int stride = gridDim.x * blockDim.x;
    float4 z4 = make_float4(0.f, 0.f, 0.f, 0.f);
    for (int t = i; t < NN * DD / 4; t += stride) ((float4*)g_sums)[t] = z4;
    for (int t = i; t < NN; t += stride) g_cnt[t] = 0.0f;
    if (i < 2 * DD) { g_est[i] = 0.0; g_vst[i] = 0.0; }
}

// ---------------- node GEMMs: x1..x4 = x @ Wm^T + bm (FFMA2 inner loop) ----------------
// block: 256 threads, 128 nodes/tile; dyn smem: xT[64][128] + Ws[64][64] + bs[64]
__global__ void __launch_bounds__(256) k_node_gemm(
    const float* __restrict__ x,
    const float* __restrict__ W1, const float* __restrict__ b1,
    const float* __restrict__ W2, const float* __restrict__ b2,
    const float* __restrict__ W3, const float* __restrict__ b3,
    const float* __restrict__ W4, const float* __restrict__ b4,
    int N)
{
    extern __shared__ float sm[];
    float* xT = sm;                 // [k][node] 64*128
    float* Ws = sm + 64 * 128;      // [k][j]    64*64
    float* bs = Ws + 64 * 64;       // [64]
    int tid = threadIdx.x;
    int nb = blockIdx.x * 128;

    {
        int nl = tid >> 1, h = tid & 1;
        int node = nb + nl;
        const float4* xr = (const float4*)(x + (size_t)node * DD + h * 32);
        #pragma unroll
        for (int q = 0; q < 8; q++) {
            float4 v = (node < N) ? __ldg(&xr[q]) : make_float4(0.f, 0.f, 0.f, 0.f);
            int kb = h * 32 + q * 4;
            xT[(kb + 0) * 128 + nl] = v.x;
            xT[(kb + 1) * 128 + nl] = v.y;
            xT[(kb + 2) * 128 + nl] = v.z;
            xT[(kb + 3) * 128 + nl] = v.w;
        }
    }

    const float* Wm[4] = {W1, W2, W3, W4};
    const float* bm[4] = {b1, b2, b3, b4};
    float* om[4] = {g_x1, g_x2, g_x3, g_x4};

    int tr = tid >> 3;       // 0..31 -> nodes tr*4..+4
    int tc = tid & 7;        // 0..7  -> feats tc*8..+8
    int fb = tc * 8;

    #pragma unroll 1
    for (int m = 0; m < 4; m++) {
        __syncthreads();
        const float* W = Wm[m];
        #pragma unroll
        for (int p = 0; p < 16; p++) {
            int idx = p * 256 + tid;            // idx = j*64 + k
            Ws[(idx & 63) * 64 + (idx >> 6)] = __ldg(&W[idx]);
        }
        if (tid < 64) bs[tid] = __ldg(&bm[m][tid]);
        __syncthreads();

        u64 acc2[4][4];
        #pragma unroll
        for (int i = 0; i < 4; i++)
            #pragma unroll
            for (int jp = 0; jp < 4; jp++) acc2[i][jp] = 0ULL;

        #pragma unroll 4
        for (int k = 0; k < 64; k++) {
            float4 a = *(const float4*)&xT[k * 128 + tr * 4];
            ulonglong2 c0 = *(const ulonglong2*)&Ws[k * 64 + fb];
            ulonglong2 c1 = *(const ulonglong2*)&Ws[k * 64 + fb + 4];
            u64 bp[4] = {c0.x, c0.y, c1.x, c1.y};
            float av[4] = {a.x, a.y, a.z, a.w};
            #pragma unroll
            for (int i = 0; i < 4; i++) {
                u64 ap = pk2(av[i], av[i]);
                #pragma unroll
                for (int jp = 0; jp < 4; jp++)
                    acc2[i][jp] = ffma2(ap, bp[jp], acc2[i][jp]);
            }
        }

        float* out = om[m];
        #pragma unroll
        for (int i = 0; i < 4; i++) {
            int node = nb + tr * 4 + i;
            if (node < N) {
                float y[8];
                #pragma unroll
                for (int jp = 0; jp < 4; jp++) upk2(acc2[i][jp], y[2 * jp], y[2 * jp + 1]);
                float4 o0 = make_float4(y[0] + bs[fb + 0], y[1] + bs[fb + 1],
                                        y[2] + bs[fb + 2], y[3] + bs[fb + 3]);
                float4 o1 = make_float4(y[4] + bs[fb + 4], y[5] + bs[fb + 5],
                                        y[6] + bs[fb + 6], y[7] + bs[fb + 7]);
                *(float4*)&out[(size_t)node * DD + fb]     = o0;
                *(float4*)&out[(size_t)node * DD + fb + 4] = o1;
            }
        }
    }
}

// ---------------- edge main pass (FFMA2 GEMM + shuffle-reduced BN stats + scatter) -------
// dyn smem: w0T[64][256] (64KB) + WeT[64][64] (16KB)
__global__ void __launch_bounds__(256) k_edge_main(
    const float* __restrict__ ea, const float* __restrict__ We, const float* __restrict__ be,
    const int* __restrict__ esrc, const int* __restrict__ edst,
    float* __restrict__ ybuf, int E)
{
    extern __shared__ float sm[];
    float* w0T = sm;                  // [k][edge] 64*256
    float* WeT = sm + 64 * 256;       // [k][j]    64*64
    __shared__ int srcs[256], dsts[256];
    __shared__ float ssum[64], ssq[64], bes[64];

    int tid = threadIdx.x;
    int e0 = blockIdx.x * 256;
    int e = e0 + tid;
    bool valid = (e < E);

    srcs[tid] = valid ? __ldg(&esrc[e]) : 0;
    dsts[tid] = valid ? __ldg(&edst[e]) : 0;
    if (tid < 64) { ssum[tid] = 0.0f; ssq[tid] = 0.0f; bes[tid] = __ldg(&be[tid]); }

    #pragma unroll
    for (int p = 0; p < 16; p++) {
        int idx = p * 256 + tid;            // idx = j*64 + k
        WeT[(idx & 63) * 64 + (idx >> 6)] = __ldg(&We[idx]);
    }
    {
        const float4* er = (const float4*)(ea + (size_t)e * DD);
        #pragma unroll
        for (int q = 0; q < 16; q++) {
            float4 v = valid ? __ldg(&er[q]) : make_float4(0.f, 0.f, 0.f, 0.f);
            w0T[(q * 4 + 0) * 256 + tid] = v.x;
            w0T[(q * 4 + 1) * 256 + tid] = v.y;
            w0T[(q * 4 + 2) * 256 + tid] = v.z;
            w0T[(q * 4 + 3) * 256 + tid] = v.w;
        }
    }
    __syncthreads();

    int tr = tid >> 3;          // 0..31 -> edges tr*8..+8
    int tc = tid & 7;           // 0..7  -> feats tc*8..+8
    int eb = tr * 8, fb = tc * 8;

    u64 acc2[8][4];
    #pragma unroll
    for (int i = 0; i < 8; i++)
        #pragma unroll
        for (int jp = 0; jp < 4; jp++) acc2[i][jp] = 0ULL;

    #pragma unroll 4
    for (int k = 0; k < 64; k++) {
        float4 a0 = *(const float4*)&w0T[k * 256 + eb];
        float4 a1 = *(const float4*)&w0T[k * 256 + eb + 4];
        ulonglong2 c0 = *(const ulonglong2*)&WeT[k * 64 + fb];
        ulonglong2 c1 = *(const ulonglong2*)&WeT[k * 64 + fb + 4];
        u64 bp[4] = {c0.x, c0.y, c1.x, c1.y};
        float av[8] = {a0.x, a0.y, a0.z, a0.w, a1.x, a1.y, a1.z, a1.w};
        #pragma unroll
        for (int i = 0; i < 8; i++) {
            u64 ap = pk2(av[i], av[i]);
            #pragma unroll
            for (int jp = 0; jp < 4; jp++)
                acc2[i][jp] = ffma2(ap, bp[jp], acc2[i][jp]);
        }
    }

    // epilogue: bias + x3[src] + x4[dst], stats, store y
    float bb[8];
    #pragma unroll
    for (int j = 0; j < 8; j++) bb[j] = bes[fb + j];

    float ps[8], pq[8];
    #pragma unroll
    for (int j = 0; j < 8; j++) { ps[j] = 0.0f; pq[j] = 0.0f; }

    #pragma unroll
    for (int i = 0; i < 8; i++) {
        int el = eb + i;
        int eg = e0 + el;
        if (eg < E) {
            int s = srcs[el], d = dsts[el];
            const float* x3r = g_x3 + (size_t)s * DD + fb;
            const float* x4r = g_x4 + (size_t)d * DD + fb;
            float4 c0 = __ldg((const float4*)x3r);
            float4 c1 = __ldg((const float4*)(x3r + 4));
            float4 d0 = __ldg((const float4*)x4r);
            float4 d1 = __ldg((const float4*)(x4r + 4));
            float g34[8] = {c0.x + d0.x, c0.y + d0.y, c0.z + d0.z, c0.w + d0.w,
                            c1.x + d1.x, c1.y + d1.y, c1.z + d1.z, c1.w + d1.w};
            float av[8];
            #pragma unroll
            for (int jp = 0; jp < 4; jp++) upk2(acc2[i][jp], av[2 * jp], av[2 * jp + 1]);
            float y[8];
            #pragma unroll
            for (int j = 0; j < 8; j++) {
                y[j] = av[j] + bb[j] + g34[j];
                ps[j] += y[j];
                pq[j] += y[j] * y[j];
            }
            float* yr = ybuf + (size_t)eg * DD + fb;
            *(float4*)yr       = make_float4(y[0], y[1], y[2], y[3]);
            *(float4*)(yr + 4) = make_float4(y[4], y[5], y[6], y[7]);
        }
    }

    // warp butterfly over lanes sharing the same tc (lanes l, l+8, l+16, l+24)
    #pragma unroll
    for (int j = 0; j < 8; j++) {
        ps[j] += __shfl_xor_sync(0xffffffffu, ps[j], 8);
        pq[j] += __shfl_xor_sync(0xffffffffu, pq[j], 8);
        ps[j] += __shfl_xor_sync(0xffffffffu, ps[j], 16);
        pq[j] += __shfl_xor_sync(0xffffffffu, pq[j], 16);
    }
    if ((tid & 31) < 8) {           // lanes 0..7: tc == lane, spread addresses within warp
        #pragma unroll
        for (int j = 0; j < 8; j++) {
            atomicAdd(&ssum[fb + j], ps[j]);
            atomicAdd(&ssq[fb + j], pq[j]);
        }
    }
    __syncthreads();
    if (tid < 64) {
        atomicAdd(&g_est[tid], (double)ssum[tid]);
        atomicAdd(&g_est[64 + tid], (double)ssq[tid]);
    }

    // scatter: sigmoid(w0)*x2[dst] -> g_sums[src], counts[src]++
    if (valid) {
        int s = srcs[tid], d = dsts[tid];
        const float4* x2r = (const float4*)(g_x2 + (size_t)d * DD);
        float* sp = g_sums + (size_t)s * DD;
        #pragma unroll
        for (int q = 0; q < 16; q++) {
            float4 xv = __ldg(&x2r[q]);
            float w0 = w0T[(q * 4 + 0) * 256 + tid];
            float w1 = w0T[(q * 4 + 1) * 256 + tid];
            float w2 = w0T[(q * 4 + 2) * 256 + tid];
            float w3 = w0T[(q * 4 + 3) * 256 + tid];
            float4 r;
            r.x = xv.x * sigf(w0);
            r.y = xv.y * sigf(w1);
            r.z = xv.z * sigf(w2);
            r.w = xv.w * sigf(w3);
            red_add_v4(sp + q * 4, r);
        }
        red_add_f32(&g_cnt[s], 1.0f);
    }
}

// ---------------- node stats: yv = x1 + sums/max(cnt,1) (in-place) + BN stats -----------
// float4 grid-stride; stride is a multiple of 16 chunks so each thread's feature slot is fixed
__global__ void __launch_bounds__(256) k_node_stats(int N) {
    __shared__ float ssum[64], ssq[64];
    int tid = threadIdx.x;
    if (tid < 64) { ssum[tid] = 0.0f; ssq[tid] = 0.0f; }
    __syncthreads();

    int i0 = blockIdx.x * blockDim.x + tid;
    int stride = gridDim.x * blockDim.x;   // multiple of 256 -> multiple of 16
    int f0 = (i0 & 15) * 4;
    float ls[4] = {0.f, 0.f, 0.f, 0.f}, lq[4] = {0.f, 0.f, 0.f, 0.f};

    for (int i = i0; i < N * 16; i += stride) {
        int node = i >> 4;
        float c = __ldg(&g_cnt[node]);
        float inv = __fdividef(1.0f, fmaxf(c, 1.0f));
        float4 a = ((const float4*)g_x1)[i];
        float4 s = ((const float4*)g_sums)[i];
        float4 yv;
        yv.x = fmaf(s.x, inv, a.x);
        yv.y = fmaf(s.y, inv, a.y);
        yv.z = fmaf(s.z, inv, a.z);
        yv.w = fmaf(s.w, inv, a.w);
        ((float4*)g_x1)[i] = yv;
        ls[0] += yv.x; lq[0] += yv.x * yv.x;
        ls[1] += yv.y; lq[1] += yv.y * yv.y;
        ls[2] += yv.z; lq[2] += yv.z * yv.z;
        ls[3] += yv.w; lq[3] += yv.w * yv.w;
    }
    // lanes l and l+16 hold the same features
    #pragma unroll
    for (int j = 0; j < 4; j++) {
        ls[j] += __shfl_xor_sync(0xffffffffu, ls[j], 16);
        lq[j] += __shfl_xor_sync(0xffffffffu, lq[j], 16);
    }
    if ((tid & 31) < 16) {
        #pragma unroll
        for (int j = 0; j < 4; j++) {
            atomicAdd(&ssum[f0 + j], ls[j]);
            atomicAdd(&ssq[f0 + j], lq[j]);
        }
    }
    __syncthreads();
    if (tid < 64) {
        atomicAdd(&g_vst[tid], (double)ssum[tid]);
        atomicAdd(&g_vst[64 + tid], (double)ssq[tid]);
    }
}

// ---------------- fold BN stats into scale/shift ----------------
__global__ void k_finalize(const float* __restrict__ vg, const float* __restrict__ vb,
                           const float* __restrict__ eg2, const float* __restrict__ eb2,
                           int N, int E)
{
    int f = threadIdx.x;
    if (f < 64) {
        double mv = g_vst[f] / (double)N;
        double varv = g_vst[64 + f] / (double)N - mv * mv;
        float scv = __ldg(&vg[f]) * rsqrtf((float)varv + 1e-5f);
        g_aff[f] = scv;
        g_aff[64 + f] = __ldg(&vb[f]) - (float)mv * scv;

        double me = g_est[f] / (double)E;
        double vare = g_est[64 + f] / (double)E - me * me;
        float sce = __ldg(&eg2[f]) * rsqrtf((float)vare + 1e-5f);
        g_aff[128 + f] = sce;
        g_aff[192 + f] = __ldg(&eb2[f]) - (float)me * sce;
    }
}

// ---------------- x_out = x + silu(bn(yv)) ----------------
__global__ void __launch_bounds__(256) k_node_out(const float* __restrict__ x,
                                                  float* __restrict__ out, int N)
{
    int i = blockIdx.x * blockDim.x + threadIdx.x;   // float4 index
    if (i < N * 16) {
        int f0 = (i & 15) * 4;
        float4 yv = *(const float4*)&g_x1[(size_t)i * 4];
        float4 xv = __ldg(((const float4*)x) + i);
        float4 sc = *(const float4*)&g_aff[f0];
        float4 sh = *(const float4*)&g_aff[64 + f0];
        float4 o;
        float z;
        z = fmaf(yv.x, sc.x, sh.x); o.x = xv.x + siluf(z);
        z = fmaf(yv.y, sc.y, sh.y); o.y = xv.y + siluf(z);
        z = fmaf(yv.z, sc.z, sh.z); o.z = xv.z + siluf(z);
        z = fmaf(yv.w, sc.w, sh.w); o.w = xv.w + siluf(z);
        ((float4*)out)[i] = o;
    }
}

// ---------------- w_out = w0 + silu(bn(y)) (y in-place in output buffer) ----------------
__global__ void __launch_bounds__(256) k_edge_out(const float* __restrict__ ea,
                                                  float* __restrict__ wout, int E)
{
    int i = blockIdx.x * blockDim.x + threadIdx.x;   // float4 index
    if (i < E * 16) {
        int f0 = (i & 15) * 4;
        float4 yv = ((const float4*)wout)[i];
        float4 w0 = __ldg(((const float4*)ea) + i);
        float4 sc = *(const float4*)&g_aff[128 + f0];
        float4 sh = *(const float4*)&g_aff[192 + f0];
        float4 o;
        float z;
        z = fmaf(yv.x, sc.x, sh.x); o.x = w0.x + siluf(z);
        z = fmaf(yv.y, sc.y, sh.y); o.y = w0.y + siluf(z);
        z = fmaf(yv.z, sc.z, sh.z); o.z = w0.z + siluf(z);
        z = fmaf(yv.w, sc.w, sh.w); o.w = w0.w + siluf(z);
        ((float4*)wout)[i] = o;
    }
}

// ---------------- launch ----------------
extern "C" void kernel_launch(void* const* d_in, const int* in_sizes, int n_in,
                              void* d_out, int out_size)
{
    const float* x  = (const float*)d_in[0];
    const float* ea = (const float*)d_in[1];
    const float* W1 = (const float*)d_in[2];  const float* b1 = (const float*)d_in[3];
    const float* W2 = (const float*)d_in[4];  const float* b2 = (const float*)d_in[5];
    const float* W3 = (const float*)d_in[6];  const float* b3 = (const float*)d_in[7];
    const float* W4 = (const float*)d_in[8];  const float* b4 = (const float*)d_in[9];
    const float* We = (const float*)d_in[10]; const float* be = (const float*)d_in[11];
    const float* vg = (const float*)d_in[12]; const float* vb = (const float*)d_in[13];
    const float* eg = (const float*)d_in[14]; const float* eb = (const float*)d_in[15];
    const int*   ei = (const int*)d_in[16];

    int N = in_sizes[0] / DD;
    int E = in_sizes[16] / 2;

    float* out = (float*)d_out;
    float* ybuf = out + (size_t)N * DD;   // w_out region doubles as y scratch

    (void)cudaFuncSetAttribute(k_node_gemm, cudaFuncAttributeMaxDynamicSharedMemorySize,
                               (64 * 128 + 64 * 64 + 64) * (int)sizeof(float));
    (void)cudaFuncSetAttribute(k_edge_main, cudaFuncAttributeMaxDynamicSharedMemorySize,
                               (64 * 256 + 64 * 64) * (int)sizeof(float));

    k_zero<<<1024, 256>>>();
    k_node_gemm<<<(N + 127) / 128, 256, (64 * 128 + 64 * 64 + 64) * sizeof(float)>>>(
        x, W1, b1, W2, b2, W3, b3, W4, b4, N);
    k_edge_main<<<(E + 255) / 256, 256, (64 * 256 + 64 * 64) * sizeof(float)>>>(
        ea, We, be, ei, ei + E, ybuf, E);
    k_node_stats<<<1184, 256>>>(N);
    k_finalize<<<1, 64>>>(vg, vb, eg, eb, N, E);
    k_node_out<<<(N * 16 + 255) / 256, 256>>>(x, out, N);
    k_edge_out<<<(E * 16 + 255) / 256, 256>>>(ea, ybuf, E);
}